// round 1
// baseline (speedup 1.0000x reference)
#include <cuda_runtime.h>
#include <math.h>

#define NN 50000
#define EE 1600000

// ---------------- scratch (device globals; no allocation allowed) ----------------
__device__ __align__(16) float g_xl[NN * 64];     // x_local @ gat_w^T
__device__ __align__(16) float g_xg[NN * 64];     // x_global @ gcn_w^T
__device__ __align__(16) float g_gat[NN * 64];    // GAT numerator accumulator (then x_l final)
__device__ __align__(16) float g_gcn[NN * 64];    // GCN numerator accumulator (then x_g final)
__device__ float g_asrc[NN];
__device__ float g_adst[NN];
__device__ float g_nind[NN];
__device__ float g_den[NN];
__device__ float g_deg[NN];
__device__ float g_dis[NN];
__device__ float g_ex[EE];
__device__ float g_ew[EE];

// ---------------- helpers ----------------
__device__ __forceinline__ void red4(float* p, float a, float b, float c, float d) {
    asm volatile("red.global.add.v4.f32 [%0], {%1,%2,%3,%4};"
                 :: "l"(p), "f"(a), "f"(b), "f"(c), "f"(d) : "memory");
}
__device__ __forceinline__ float elu1(float v) { return v > 0.f ? v : (expf(v) - 1.f); }

// ---------------- per-node noise MLP: nind[i] = fc2( elu(fc1(nf[i])) ) ----------------
__global__ void k_nind(const float* __restrict__ nf, const float* __restrict__ fc1w,
                       const float* __restrict__ fc1b, const float* __restrict__ fc2w,
                       const float* __restrict__ fc2b) {
    __shared__ float w1[100], b1[10], w2[10], b2s;
    int tid = threadIdx.x;
    if (tid < 100) w1[tid] = fc1w[tid];
    if (tid < 10) { b1[tid] = fc1b[tid]; w2[tid] = fc2w[tid]; }
    if (tid == 0) b2s = fc2b[0];
    __syncthreads();
    int i = blockIdx.x * blockDim.x + tid;
    if (i >= NN) return;
    float x[10];
#pragma unroll
    for (int k = 0; k < 10; k++) x[k] = nf[i * 10 + k];
    float acc = b2s;
#pragma unroll
    for (int j = 0; j < 10; j++) {
        float h = b1[j];
#pragma unroll
        for (int k = 0; k < 10; k++) h += x[k] * w1[j * 10 + k];
        h = elu1(h);
        acc += h * w2[j];
    }
    g_nind[i] = acc;
}

// ---------------- GEMM: out[n][64] = sum_k X[n][k] * W[h][k]   (K=128, H=64) ----------------
// block: 256 threads, 64 rows per block. Dynamic smem: 2 * 128 * 68 floats = 69632 B.
__global__ void k_gemm(const float* __restrict__ X, const float* __restrict__ W,
                       float* __restrict__ out, int nrows) {
    extern __shared__ float sm[];
    float (*Xs)[68] = (float(*)[68])sm;            // k-major
    float (*Ws)[68] = (float(*)[68])(sm + 128 * 68);
    int tid = threadIdx.x;
    int r0 = blockIdx.x * 64;
#pragma unroll
    for (int i = 0; i < 32; i++) {
        int idx = tid + i * 256;
        int h = idx >> 7, k = idx & 127;
        Ws[k][h] = W[idx];
    }
#pragma unroll
    for (int i = 0; i < 32; i++) {
        int idx = tid + i * 256;
        int n = idx >> 7, k = idx & 127;
        int r = r0 + n;
        Xs[k][n] = (r < nrows) ? X[r * 128 + k] : 0.f;
    }
    __syncthreads();
    int ty = tid >> 4, tx = tid & 15;
    int n0 = ty * 4, h0 = tx * 4;
    float acc[4][4] = {};
#pragma unroll 4
    for (int k = 0; k < 128; k++) {
        float4 xv = *(const float4*)&Xs[k][n0];
        float4 wv = *(const float4*)&Ws[k][h0];
        float xs[4] = {xv.x, xv.y, xv.z, xv.w};
        float ws[4] = {wv.x, wv.y, wv.z, wv.w};
#pragma unroll
        for (int i = 0; i < 4; i++)
#pragma unroll
            for (int j = 0; j < 4; j++) acc[i][j] += xs[i] * ws[j];
    }
#pragma unroll
    for (int i = 0; i < 4; i++) {
        int r = r0 + n0 + i;
        if (r < nrows) {
            float4 o = make_float4(acc[i][0], acc[i][1], acc[i][2], acc[i][3]);
            *(float4*)&out[r * 64 + h0] = o;
        }
    }
}

// ---------------- per-node attention scalars a_src, a_dst ----------------
__global__ void k_node_attn(const float* __restrict__ att_s, const float* __restrict__ att_d) {
    __shared__ float ss[64], sd[64];
    int tid = threadIdx.x;
    if (tid < 64) { ss[tid] = att_s[tid]; sd[tid] = att_d[tid]; }
    __syncthreads();
    int i = blockIdx.x * blockDim.x + tid;
    if (i >= NN) return;
    const float4* row = (const float4*)(g_xl + i * 64);
    float a = 0.f, b = 0.f;
#pragma unroll
    for (int j = 0; j < 16; j++) {
        float4 v = row[j];
        a += v.x * ss[4 * j] + v.y * ss[4 * j + 1] + v.z * ss[4 * j + 2] + v.w * ss[4 * j + 3];
        b += v.x * sd[4 * j] + v.y * sd[4 * j + 1] + v.z * sd[4 * j + 2] + v.w * sd[4 * j + 3];
    }
    g_asrc[i] = a;
    g_adst[i] = b;
}

// ---------------- self-loop init: den = exp(lrelu(a_s+a_d)), deg = 1 ----------------
__global__ void k_selfinit() {
    int i = blockIdx.x * blockDim.x + threadIdx.x;
    if (i >= NN) return;
    float e = g_asrc[i] + g_adst[i];
    e = e > 0.f ? e : 0.2f * e;
    g_den[i] = expf(e);
    g_deg[i] = 1.f;
}

// ---------------- accumulator init: gat = ex_self * xl, gcn = 0 ----------------
__global__ void k_initvec() {
    int t = blockIdx.x * blockDim.x + threadIdx.x;
    if (t >= NN * 16) return;
    int n = t >> 4, l = t & 15;
    float ex = g_den[n];
    float4 v = ((const float4*)g_xl)[n * 16 + l];
    ((float4*)g_gat)[n * 16 + l] = make_float4(ex * v.x, ex * v.y, ex * v.z, ex * v.w);
    ((float4*)g_gcn)[n * 16 + l] = make_float4(0.f, 0.f, 0.f, 0.f);
}

// ---------------- edge scalar pass: compute ex, ew; accumulate den, deg ----------------
__global__ void k_edge_scalar(const int* __restrict__ ei, const float* __restrict__ coord) {
    int t = blockIdx.x * blockDim.x + threadIdx.x;
    if (t >= EE) return;
    int s = ei[t], d = ei[EE + t];
    float ni = g_nind[s];
    float2 cs = ((const float2*)coord)[s];
    float2 cd = ((const float2*)coord)[d];
    float dx = cs.x - cd.x, dy = cs.y - cd.y;
    float gw = expf(-(dx * dx + dy * dy) * (1.0f / 1800.0f));
    float z = gw * (1.f + ni) - 1.f;
    float w = 0.1f + 1.9f / (1.f + expf(-z));
    bool m = (w >= 0.2f);
    float e = g_asrc[s] + g_adst[d];
    e = e > 0.f ? e : 0.2f * e;
    float ex = m ? expf(e) : 0.f;
    float ew = m ? w : 0.f;
    g_ex[t] = ex;
    g_ew[t] = ew;
    if (m) {
        atomicAdd(&g_den[d], ex);
        atomicAdd(&g_deg[d], ew);
    }
}

// ---------------- dis = rsqrt(deg) ----------------
__global__ void k_dis() {
    int i = blockIdx.x * blockDim.x + threadIdx.x;
    if (i >= NN) return;
    g_dis[i] = rsqrtf(g_deg[i]);
}

// ---------------- vector edge pass: 16 threads/edge, scatter both branches ----------------
__global__ void k_edge_vec(const int* __restrict__ ei) {
    int gt = blockIdx.x * blockDim.x + threadIdx.x;
    int t = gt >> 4;
    if (t >= EE) return;
    float ew = g_ew[t];
    if (ew == 0.f) return;  // masked edge (ex==0 too)
    int l = gt & 15;
    int s = ei[t], d = ei[EE + t];
    float ex = g_ex[t];
    float c = ew * g_dis[s];
    float4 v = ((const float4*)g_xl)[s * 16 + l];
    red4((float*)&((float4*)g_gat)[d * 16 + l], ex * v.x, ex * v.y, ex * v.z, ex * v.w);
    float4 u = ((const float4*)g_xg)[s * 16 + l];
    red4((float*)&((float4*)g_gcn)[d * 16 + l], c * u.x, c * u.y, c * u.z, c * u.w);
}

// ---------------- finalize branches: x_l = elu(gat/den + b), x_g = relu(dis*(gcn + dis*xg) + b) --------
__global__ void k_finalprep(const float* __restrict__ gatb, const float* __restrict__ gcnb) {
    int t = blockIdx.x * blockDim.x + threadIdx.x;
    if (t >= NN * 16) return;
    int n = t >> 4, l = t & 15;
    float inv_den = 1.f / g_den[n];
    float dis = g_dis[n];
    float4 g = ((const float4*)g_gat)[n * 16 + l];
    float4 bb = ((const float4*)gatb)[l];
    float4 r;
    r.x = elu1(g.x * inv_den + bb.x);
    r.y = elu1(g.y * inv_den + bb.y);
    r.z = elu1(g.z * inv_den + bb.z);
    r.w = elu1(g.w * inv_den + bb.w);
    ((float4*)g_gat)[n * 16 + l] = r;
    float4 cc = ((const float4*)g_gcn)[n * 16 + l];
    float4 xg = ((const float4*)g_xg)[n * 16 + l];
    float4 b2 = ((const float4*)gcnb)[l];
    float4 q;
    q.x = fmaxf(dis * (cc.x + dis * xg.x) + b2.x, 0.f);
    q.y = fmaxf(dis * (cc.y + dis * xg.y) + b2.y, 0.f);
    q.z = fmaxf(dis * (cc.z + dis * xg.z) + b2.z, 0.f);
    q.w = fmaxf(dis * (cc.w + dis * xg.w) + b2.w, 0.f);
    ((float4*)g_gcn)[n * 16 + l] = q;
}

// ---------------- fusion: out = w2 @ relu(W1 @ [x_l; x_g] + b1) + b2 ----------------
__global__ void k_fusion(const float* __restrict__ W1, const float* __restrict__ b1,
                         const float* __restrict__ w2, const float* __restrict__ b2,
                         float* __restrict__ out, int nrows) {
    extern __shared__ float sm[];
    float (*Xs)[68] = (float(*)[68])sm;
    float (*Ws)[68] = (float(*)[68])(sm + 128 * 68);
    int tid = threadIdx.x;
    int r0 = blockIdx.x * 64;
#pragma unroll
    for (int i = 0; i < 32; i++) {
        int idx = tid + i * 256;
        int h = idx >> 7, k = idx & 127;
        Ws[k][h] = W1[idx];
    }
#pragma unroll
    for (int i = 0; i < 32; i++) {
        int idx = tid + i * 256;
        int n = idx >> 7, k = idx & 127;
        int r = r0 + n;
        float v = 0.f;
        if (r < nrows) v = (k < 64) ? g_gat[r * 64 + k] : g_gcn[r * 64 + (k - 64)];
        Xs[k][n] = v;
    }
    __syncthreads();
    int ty = tid >> 4, tx = tid & 15;
    int n0 = ty * 4, h0 = tx * 4;
    float acc[4][4] = {};
#pragma unroll 4
    for (int k = 0; k < 128; k++) {
        float4 xv = *(const float4*)&Xs[k][n0];
        float4 wv = *(const float4*)&Ws[k][h0];
        float xs[4] = {xv.x, xv.y, xv.z, xv.w};
        float ws[4] = {wv.x, wv.y, wv.z, wv.w};
#pragma unroll
        for (int i = 0; i < 4; i++)
#pragma unroll
            for (int j = 0; j < 4; j++) acc[i][j] += xs[i] * ws[j];
    }
    float b1v[4], w2v[4];
#pragma unroll
    for (int j = 0; j < 4; j++) { b1v[j] = b1[h0 + j]; w2v[j] = w2[h0 + j]; }
    float part[4];
#pragma unroll
    for (int i = 0; i < 4; i++) {
        float p = 0.f;
#pragma unroll
        for (int j = 0; j < 4; j++) p += fmaxf(acc[i][j] + b1v[j], 0.f) * w2v[j];
        part[i] = p;
    }
#pragma unroll
    for (int off = 8; off >= 1; off >>= 1)
#pragma unroll
        for (int i = 0; i < 4; i++) part[i] += __shfl_down_sync(0xffffffffu, part[i], off);
    if (tx == 0) {
        float bb = b2[0];
#pragma unroll
        for (int i = 0; i < 4; i++) {
            int r = r0 + n0 + i;
            if (r < nrows) out[r] = part[i] + bb;
        }
    }
}

// ---------------- launch ----------------
extern "C" void kernel_launch(void* const* d_in, const int* in_sizes, int n_in,
                              void* d_out, int out_size) {
    const float* x_local  = (const float*)d_in[0];
    const float* x_global = (const float*)d_in[1];
    const float* nf       = (const float*)d_in[2];
    const float* coord    = (const float*)d_in[3];
    const int*   ei       = (const int*)d_in[4];
    const float* fc1w     = (const float*)d_in[5];
    const float* fc1b     = (const float*)d_in[6];
    const float* fc2w     = (const float*)d_in[7];
    const float* fc2b     = (const float*)d_in[8];
    const float* gat_w    = (const float*)d_in[9];
    const float* att_s    = (const float*)d_in[10];
    const float* att_d    = (const float*)d_in[11];
    const float* gat_b    = (const float*)d_in[12];
    const float* gcn_w    = (const float*)d_in[13];
    const float* gcn_b    = (const float*)d_in[14];
    const float* fus_w1   = (const float*)d_in[15];
    const float* fus_b1   = (const float*)d_in[16];
    const float* fus_w2   = (const float*)d_in[17];
    const float* fus_b2   = (const float*)d_in[18];
    float* out = (float*)d_out;

    const int SMEM = 2 * 128 * 68 * (int)sizeof(float);  // 69632
    cudaFuncSetAttribute(k_gemm,   cudaFuncAttributeMaxDynamicSharedMemorySize, SMEM);
    cudaFuncSetAttribute(k_fusion, cudaFuncAttributeMaxDynamicSharedMemorySize, SMEM);

    float *pxl, *pxg;
    cudaGetSymbolAddress((void**)&pxl, g_xl);
    cudaGetSymbolAddress((void**)&pxg, g_xg);

    const int NB_N   = (NN + 255) / 256;        // 196
    const int NB_N16 = (NN * 16 + 255) / 256;   // 3125
    const int NB_E   = (EE + 255) / 256;        // 6250
    const int NB_E16 = (EE * 16 + 255) / 256;   // 100000
    const int NB_G   = (NN + 63) / 64;          // 782

    k_nind<<<NB_N, 256>>>(nf, fc1w, fc1b, fc2w, fc2b);
    k_gemm<<<NB_G, 256, SMEM>>>(x_local, gat_w, pxl, NN);
    k_gemm<<<NB_G, 256, SMEM>>>(x_global, gcn_w, pxg, NN);
    k_node_attn<<<NB_N, 256>>>(att_s, att_d);
    k_selfinit<<<NB_N, 256>>>();
    k_initvec<<<NB_N16, 256>>>();
    k_edge_scalar<<<NB_E, 256>>>(ei, coord);
    k_dis<<<NB_N, 256>>>();
    k_edge_vec<<<NB_E16, 256>>>(ei);
    k_finalprep<<<NB_N16, 256>>>(gat_b, gcn_b);
    k_fusion<<<NB_G, 256, SMEM>>>(fus_w1, fus_b1, fus_w2, fus_b2, out, NN);
}